// round 2
// baseline (speedup 1.0000x reference)
#include <cuda_runtime.h>
#include <cub/cub.cuh>
#include <cstdint>

// ---------------- problem constants ----------------
#define BATCH   8
#define NPTS    131072
#define PATCHW  32
#define STRIDEW 16
#define LWIN    8191                    // (131072-32)/16 + 1
#define BL      (BATCH*LWIN)            // 65528
#define BN      (BATCH*NPTS)            // 1048576
#define TOK     (BL*256)                // 16775168 tokens elems
#define CEN     (BL*3)                  // 196584 centroid elems
#define IDXN    BN                      // 1048576 sort_idx elems

// ---------------- static device scratch (no allocation allowed) ----------------
__device__ __align__(256) unsigned long long g_keys[BN];
__device__ __align__(256) unsigned long long g_keys_out[BN];
__device__ __align__(256) unsigned char      g_temp[128u * 1024u * 1024u];
__device__ unsigned                          g_mm[48];      // [b][axis][min,max] encoded
__device__ __align__(16) float               g_sp[BN * 3];  // sorted points
__device__ float                             g_cent[BL * 3];
__device__ __align__(16) float               g_comb[(size_t)BL * 256];

// ---------------- helpers ----------------
__device__ __forceinline__ unsigned fenc(float f) {
    unsigned u = __float_as_uint(f);
    return (u & 0x80000000u) ? ~u : (u | 0x80000000u);
}
__device__ __forceinline__ float fdec(unsigned u) {
    return (u & 0x80000000u) ? __uint_as_float(u ^ 0x80000000u)
                             : __uint_as_float(~u);
}
// spread 10 bits so bit i -> bit 3i (matches reference _expand_bits for v<1024)
__device__ __forceinline__ unsigned expand10(unsigned v) {
    v &= 0x3FFu;
    v = (v | (v << 16)) & 0x030000FFu;
    v = (v | (v << 8))  & 0x0300F00Fu;
    v = (v | (v << 4))  & 0x030C30C3u;
    v = (v | (v << 2))  & 0x09249249u;
    return v;
}

// ---------------- K0: reset min/max ----------------
__global__ void k_reset() {
    int t = threadIdx.x;
    if (t < 48) g_mm[t] = (t & 1) ? 0u : 0xFFFFFFFFu;
}

// ---------------- K1: per-(batch,axis) min/max ----------------
__global__ void __launch_bounds__(256) k_minmax(const float* __restrict__ pts) {
    int b = blockIdx.x >> 6, chunk = blockIdx.x & 63, t = threadIdx.x;
    unsigned mn0 = ~0u, mn1 = ~0u, mn2 = ~0u, mx0 = 0u, mx1 = 0u, mx2 = 0u;
    size_t base = (size_t)b * NPTS + (size_t)chunk * 2048;
    for (int j = t; j < 2048; j += 256) {
        const float* p = pts + (base + j) * 3;
        unsigned e0 = fenc(p[0]), e1 = fenc(p[1]), e2 = fenc(p[2]);
        mn0 = min(mn0, e0); mx0 = max(mx0, e0);
        mn1 = min(mn1, e1); mx1 = max(mx1, e1);
        mn2 = min(mn2, e2); mx2 = max(mx2, e2);
    }
    mn0 = __reduce_min_sync(0xffffffffu, mn0); mx0 = __reduce_max_sync(0xffffffffu, mx0);
    mn1 = __reduce_min_sync(0xffffffffu, mn1); mx1 = __reduce_max_sync(0xffffffffu, mx1);
    mn2 = __reduce_min_sync(0xffffffffu, mn2); mx2 = __reduce_max_sync(0xffffffffu, mx2);
    __shared__ unsigned s[6];
    if (t < 6) s[t] = (t < 3) ? 0xFFFFFFFFu : 0u;
    __syncthreads();
    if ((t & 31) == 0) {
        atomicMin(&s[0], mn0); atomicMin(&s[1], mn1); atomicMin(&s[2], mn2);
        atomicMax(&s[3], mx0); atomicMax(&s[4], mx1); atomicMax(&s[5], mx2);
    }
    __syncthreads();
    if (t < 3)                 atomicMin(&g_mm[b * 6 + t * 2], s[t]);
    else if (t < 6)            atomicMax(&g_mm[b * 6 + (t - 3) * 2 + 1], s[t]);
}

// ---------------- K2: morton keys (match XLA's div->reciprocal-mul rewrite) ----------------
__global__ void __launch_bounds__(256) k_keys(const float* __restrict__ pts) {
    int i = blockIdx.x * 256 + threadIdx.x;
    int b = i >> 17;
    int n = i & (NPTS - 1);
    const float* p = pts + (size_t)i * 3;
    unsigned q[3];
#pragma unroll
    for (int a = 0; a < 3; a++) {
        float mn = fdec(g_mm[b * 6 + a * 2]);
        float mx = fdec(g_mm[b * 6 + a * 2 + 1]);
        float sc = fmaxf(__fsub_rn(mx, mn), 1e-8f);       // clip(max-min, 1e-8)
        // XLA rewrites divide(X, broadcast(scale)) -> multiply(X, broadcast(1/scale)).
        // Match that: correctly-rounded reciprocal, then RN multiply.
        float r  = __frcp_rn(sc);
        float nr = __fmul_rn(__fsub_rn(p[a], mn), r);     // (p - pmin) * (1/scale)
        float tq = __fmul_rn(nr, 1023.0f);                // * (RES-1)
        int qi = (int)tq;                                 // trunc toward zero
        qi = max(0, min(qi, 1023));
        q[a] = (unsigned)qi;
    }
    unsigned mort = (expand10(q[0]) << 2) | (expand10(q[1]) << 1) | expand10(q[2]);
    g_keys[i] = ((unsigned long long)(unsigned)b << 47) |
                ((unsigned long long)mort << 17) | (unsigned)n;
}

// ---------------- K4: unpack sort_idx + gather sorted points ----------------
__global__ void __launch_bounds__(256) k_gather(const float* __restrict__ pts,
                                                float* __restrict__ out, int write_idx) {
    int i = blockIdx.x * 256 + threadIdx.x;
    int b = i >> 17;
    unsigned long long k = g_keys_out[i];
    int idx = (int)(k & 0x1FFFFull);
    if (write_idx) out[TOK + CEN + i] = (float)idx;
    const float* s = pts + (((size_t)b << 17) + (size_t)idx) * 3;
    float* d = g_sp + (size_t)i * 3;
    d[0] = s[0]; d[1] = s[1]; d[2] = s[2];
}

// ---------------- K5: centroids ----------------
__global__ void __launch_bounds__(128) k_cent(float* __restrict__ out, int write_cent) {
    int m = blockIdx.x * 128 + threadIdx.x;
    if (m >= BL) return;
    int b = m / LWIN, l = m - b * LWIN;
    const float* sp = g_sp + ((size_t)b * NPTS + (size_t)l * STRIDEW) * 3;
    float sx = 0.f, sy = 0.f, sz = 0.f;
#pragma unroll
    for (int p = 0; p < PATCHW; p++) {
        sx += sp[p * 3 + 0]; sy += sp[p * 3 + 1]; sz += sp[p * 3 + 2];
    }
    float cx = sx / 32.0f, cy = sy / 32.0f, cz = sz / 32.0f;
    g_cent[m * 3 + 0] = cx; g_cent[m * 3 + 1] = cy; g_cent[m * 3 + 2] = cz;
    if (write_cent) {
        out[TOK + m * 3 + 0] = cx; out[TOK + m * 3 + 1] = cy; out[TOK + m * 3 + 2] = cz;
    }
}

// ---------------- K6: per-window MLP + maxpool + pos MLP -> combined(256) ----------------
__global__ void __launch_bounds__(128) k_mlp(const float* __restrict__ W1, const float* __restrict__ b1,
                                             const float* __restrict__ W2, const float* __restrict__ b2,
                                             const float* __restrict__ Wp1, const float* __restrict__ bp1,
                                             const float* __restrict__ Wp2, const float* __restrict__ bp2) {
    __shared__ float locx[32], locy[32], locz[32];
    __shared__ float hp[64];
    __shared__ float c_sm[3];
    __shared__ __align__(16) float h_sm[2048];   // [32 points][64 ch]

    int m = blockIdx.x;
    int t = threadIdx.x;
    int b = m / LWIN, l = m - b * LWIN;

    if (t < 3) c_sm[t] = g_cent[m * 3 + t];
    __syncthreads();

    const float* sp = g_sp + ((size_t)b * NPTS + (size_t)l * STRIDEW) * 3;
    if (t < 32) {
        locx[t] = sp[t * 3 + 0] - c_sm[0];
        locy[t] = sp[t * 3 + 1] - c_sm[1];
        locz[t] = sp[t * 3 + 2] - c_sm[2];
    }
    if (t < 64) {
        float v = fmaf(c_sm[2], Wp1[128 + t],
                  fmaf(c_sm[1], Wp1[64 + t],
                  fmaf(c_sm[0], Wp1[t], bp1[t])));
        hp[t] = fmaxf(v, 0.f);
    }
    __syncthreads();

    // h = relu(local @ W1 + b1) : 32x64, each thread 16 entries
#pragma unroll
    for (int j = 0; j < 16; j++) {
        int i = t + 128 * j;
        int p = i >> 6, d = i & 63;
        float v = fmaf(locz[p], W1[128 + d],
                  fmaf(locy[p], W1[64 + d],
                  fmaf(locx[p], W1[d], b1[d])));
        h_sm[i] = fmaxf(v, 0.f);
    }
    // W2 column for this output channel into registers
    float w2r[64];
#pragma unroll
    for (int d = 0; d < 64; d++) w2r[d] = W2[d * 128 + t];
    __syncthreads();

    float geo = 0.f;                       // feat >= 0, so init 0 == max over relu
    float b2e = b2[t];
    for (int p = 0; p < 32; p++) {
        const float4* h4 = reinterpret_cast<const float4*>(h_sm + p * 64);
        float f0 = b2e, f1 = 0.f;
#pragma unroll
        for (int i = 0; i < 8; i++) {
            float4 a = h4[2 * i], c = h4[2 * i + 1];
            f0 = fmaf(a.x, w2r[8 * i + 0], f0);
            f0 = fmaf(a.y, w2r[8 * i + 1], f0);
            f0 = fmaf(a.z, w2r[8 * i + 2], f0);
            f0 = fmaf(a.w, w2r[8 * i + 3], f0);
            f1 = fmaf(c.x, w2r[8 * i + 4], f1);
            f1 = fmaf(c.y, w2r[8 * i + 5], f1);
            f1 = fmaf(c.z, w2r[8 * i + 6], f1);
            f1 = fmaf(c.w, w2r[8 * i + 7], f1);
        }
        geo = fmaxf(geo, f0 + f1);
    }
    float pos = bp2[t];
#pragma unroll
    for (int d = 0; d < 64; d++) pos = fmaf(hp[d], Wp2[d * 128 + t], pos);

    size_t o = (size_t)m * 256 + t;
    g_comb[o]       = geo;
    g_comb[o + 128] = pos;
}

// ---------------- K7: tokens = combined(65528x256) @ Wproj(256x256) + bproj ----------------
__global__ void __launch_bounds__(256) k_proj(const float* __restrict__ Wp,
                                              const float* __restrict__ bp,
                                              float* __restrict__ out) {
    __shared__ __align__(16) float a_s[32][68];  // [k][row], padded
    __shared__ __align__(16) float b_s[32][64];  // [k][col]
    int row0 = blockIdx.x * 64, col0 = blockIdx.y * 64;
    int t = threadIdx.x;
    int tr = t >> 4, tc = t & 15;
    int r0 = tr * 4, o0 = tc * 4;
    float acc[4][4] = {};

    for (int k0 = 0; k0 < 256; k0 += 32) {
        int kk4 = (t & 7) * 4;
        int r = t >> 3;
#pragma unroll
        for (int pass = 0; pass < 2; pass++) {
            int rr = r + 32 * pass;
            int grow = row0 + rr;
            float4 v = make_float4(0.f, 0.f, 0.f, 0.f);
            if (grow < BL)
                v = *reinterpret_cast<const float4*>(g_comb + (size_t)grow * 256 + k0 + kk4);
            a_s[kk4 + 0][rr] = v.x; a_s[kk4 + 1][rr] = v.y;
            a_s[kk4 + 2][rr] = v.z; a_s[kk4 + 3][rr] = v.w;
        }
#pragma unroll
        for (int j = 0; j < 8; j++) {
            int idx = t + 256 * j;
            int kk = idx >> 6, o = idx & 63;
            b_s[kk][o] = Wp[(k0 + kk) * 256 + col0 + o];
        }
        __syncthreads();
#pragma unroll
        for (int kk = 0; kk < 32; kk++) {
            float4 a  = *reinterpret_cast<const float4*>(&a_s[kk][r0]);
            float4 bb = *reinterpret_cast<const float4*>(&b_s[kk][o0]);
            acc[0][0] = fmaf(a.x, bb.x, acc[0][0]); acc[0][1] = fmaf(a.x, bb.y, acc[0][1]);
            acc[0][2] = fmaf(a.x, bb.z, acc[0][2]); acc[0][3] = fmaf(a.x, bb.w, acc[0][3]);
            acc[1][0] = fmaf(a.y, bb.x, acc[1][0]); acc[1][1] = fmaf(a.y, bb.y, acc[1][1]);
            acc[1][2] = fmaf(a.y, bb.z, acc[1][2]); acc[1][3] = fmaf(a.y, bb.w, acc[1][3]);
            acc[2][0] = fmaf(a.z, bb.x, acc[2][0]); acc[2][1] = fmaf(a.z, bb.y, acc[2][1]);
            acc[2][2] = fmaf(a.z, bb.z, acc[2][2]); acc[2][3] = fmaf(a.z, bb.w, acc[2][3]);
            acc[3][0] = fmaf(a.w, bb.x, acc[3][0]); acc[3][1] = fmaf(a.w, bb.y, acc[3][1]);
            acc[3][2] = fmaf(a.w, bb.z, acc[3][2]); acc[3][3] = fmaf(a.w, bb.w, acc[3][3]);
        }
        __syncthreads();
    }
    float4 bias = *reinterpret_cast<const float4*>(bp + col0 + o0);
#pragma unroll
    for (int i = 0; i < 4; i++) {
        int row = row0 + r0 + i;
        if (row < BL) {
            float4 v = make_float4(acc[i][0] + bias.x, acc[i][1] + bias.y,
                                   acc[i][2] + bias.z, acc[i][3] + bias.w);
            *reinterpret_cast<float4*>(out + (size_t)row * 256 + col0 + o0) = v;
        }
    }
}

// ---------------- launch ----------------
extern "C" void kernel_launch(void* const* d_in, const int* in_sizes, int n_in,
                              void* d_out, int out_size) {
    const float* points = (const float*)d_in[0];
    const float* W1   = (const float*)d_in[1];
    const float* b1   = (const float*)d_in[2];
    const float* W2   = (const float*)d_in[3];
    const float* b2   = (const float*)d_in[4];
    const float* Wp1  = (const float*)d_in[5];
    const float* bp1  = (const float*)d_in[6];
    const float* Wp2  = (const float*)d_in[7];
    const float* bp2  = (const float*)d_in[8];
    const float* Wproj = (const float*)d_in[9];
    const float* bproj = (const float*)d_in[10];
    float* out = (float*)d_out;

    int write_cent = (out_size >= TOK + CEN) ? 1 : 0;
    int write_idx  = (out_size >= TOK + CEN + IDXN) ? 1 : 0;

    k_reset<<<1, 64>>>();
    k_minmax<<<BATCH * 64, 256>>>(points);
    k_keys<<<BN / 256, 256>>>(points);

    void* d_temp = nullptr;
    unsigned long long* kin = nullptr;
    unsigned long long* kout = nullptr;
    cudaGetSymbolAddress(&d_temp, g_temp);
    cudaGetSymbolAddress((void**)&kin, g_keys);
    cudaGetSymbolAddress((void**)&kout, g_keys_out);

    size_t temp_bytes = 0;
    cub::DeviceRadixSort::SortKeys(nullptr, temp_bytes, kin, kout, BN, 0, 50);
    if (temp_bytes <= sizeof(g_temp)) {
        cub::DeviceRadixSort::SortKeys(d_temp, temp_bytes, kin, kout, BN, 0, 50);
    }

    k_gather<<<BN / 256, 256>>>(points, out, write_idx);
    k_cent<<<(BL + 127) / 128, 128>>>(out, write_cent);
    k_mlp<<<BL, 128>>>(W1, b1, W2, b2, Wp1, bp1, Wp2, bp2);
    k_proj<<<dim3((BL + 63) / 64, 4), 256>>>(Wproj, bproj, out);
}

// round 4
// speedup vs baseline: 1.0136x; 1.0136x over previous
#include <cuda_runtime.h>
#include <cub/cub.cuh>
#include <cstdint>

// ---------------- problem constants ----------------
#define BATCH   8
#define NPTS    131072
#define PATCHW  32
#define STRIDEW 16
#define LWIN    8191                    // (131072-32)/16 + 1
#define BL      (BATCH*LWIN)            // 65528
#define BN      (BATCH*NPTS)            // 1048576
#define TOK     (BL*256)                // 16775168 tokens elems
#define CEN     (BL*3)                  // 196584 centroid elems
#define IDXN    BN                      // 1048576 sort_idx elems

// ---------------- static device scratch (no allocation allowed) ----------------
__device__ __align__(256) unsigned long long g_keys[BN];
__device__ __align__(256) unsigned long long g_keys_out[BN];
__device__ __align__(256) unsigned char      g_temp[128u * 1024u * 1024u];
__device__ unsigned                          g_mm[48];      // [b][axis][min,max] encoded
__device__ __align__(16) float               g_sp[BN * 3];  // sorted points
__device__ float                             g_cent[BL * 3];
__device__ __align__(16) float               g_comb[(size_t)BL * 256];

// ---------------- f32x2 packed helpers (sm_103a FFMA2) ----------------
__device__ __forceinline__ unsigned long long pack2(float lo, float hi) {
    unsigned long long r;
    asm("mov.b64 %0, {%1, %2};" : "=l"(r) : "f"(lo), "f"(hi));
    return r;
}
__device__ __forceinline__ float2 unpack2(unsigned long long v) {
    float2 r;
    asm("mov.b64 {%0, %1}, %2;" : "=f"(r.x), "=f"(r.y) : "l"(v));
    return r;
}
__device__ __forceinline__ void fma2(unsigned long long& d, unsigned long long a,
                                     unsigned long long b, unsigned long long c) {
    asm("fma.rn.f32x2 %0, %1, %2, %3;" : "=l"(d) : "l"(a), "l"(b), "l"(c));
}
__device__ __forceinline__ unsigned long long add2(unsigned long long a, unsigned long long b) {
    unsigned long long r;
    asm("add.rn.f32x2 %0, %1, %2;" : "=l"(r) : "l"(a), "l"(b));
    return r;
}

// ---------------- helpers ----------------
__device__ __forceinline__ unsigned fenc(float f) {
    unsigned u = __float_as_uint(f);
    return (u & 0x80000000u) ? ~u : (u | 0x80000000u);
}
__device__ __forceinline__ float fdec(unsigned u) {
    return (u & 0x80000000u) ? __uint_as_float(u ^ 0x80000000u)
                             : __uint_as_float(~u);
}
// spread 10 bits so bit i -> bit 3i (matches reference _expand_bits for v<1024)
__device__ __forceinline__ unsigned expand10(unsigned v) {
    v &= 0x3FFu;
    v = (v | (v << 16)) & 0x030000FFu;
    v = (v | (v << 8))  & 0x0300F00Fu;
    v = (v | (v << 4))  & 0x030C30C3u;
    v = (v | (v << 2))  & 0x09249249u;
    return v;
}

// ---------------- K0: reset min/max ----------------
__global__ void k_reset() {
    int t = threadIdx.x;
    if (t < 48) g_mm[t] = (t & 1) ? 0u : 0xFFFFFFFFu;
}

// ---------------- K1: per-(batch,axis) min/max ----------------
__global__ void __launch_bounds__(256) k_minmax(const float* __restrict__ pts) {
    int b = blockIdx.x >> 6, chunk = blockIdx.x & 63, t = threadIdx.x;
    unsigned mn0 = ~0u, mn1 = ~0u, mn2 = ~0u, mx0 = 0u, mx1 = 0u, mx2 = 0u;
    size_t base = (size_t)b * NPTS + (size_t)chunk * 2048;
    for (int j = t; j < 2048; j += 256) {
        const float* p = pts + (base + j) * 3;
        unsigned e0 = fenc(p[0]), e1 = fenc(p[1]), e2 = fenc(p[2]);
        mn0 = min(mn0, e0); mx0 = max(mx0, e0);
        mn1 = min(mn1, e1); mx1 = max(mx1, e1);
        mn2 = min(mn2, e2); mx2 = max(mx2, e2);
    }
    mn0 = __reduce_min_sync(0xffffffffu, mn0); mx0 = __reduce_max_sync(0xffffffffu, mx0);
    mn1 = __reduce_min_sync(0xffffffffu, mn1); mx1 = __reduce_max_sync(0xffffffffu, mx1);
    mn2 = __reduce_min_sync(0xffffffffu, mn2); mx2 = __reduce_max_sync(0xffffffffu, mx2);
    __shared__ unsigned s[6];
    if (t < 6) s[t] = (t < 3) ? 0xFFFFFFFFu : 0u;
    __syncthreads();
    if ((t & 31) == 0) {
        atomicMin(&s[0], mn0); atomicMin(&s[1], mn1); atomicMin(&s[2], mn2);
        atomicMax(&s[3], mx0); atomicMax(&s[4], mx1); atomicMax(&s[5], mx2);
    }
    __syncthreads();
    if (t < 3)                 atomicMin(&g_mm[b * 6 + t * 2], s[t]);
    else if (t < 6)            atomicMax(&g_mm[b * 6 + (t - 3) * 2 + 1], s[t]);
}

// ---------------- K2: morton keys (match XLA's div->reciprocal-mul rewrite) ----------------
__global__ void __launch_bounds__(256) k_keys(const float* __restrict__ pts) {
    int i = blockIdx.x * 256 + threadIdx.x;
    int b = i >> 17;
    int n = i & (NPTS - 1);
    const float* p = pts + (size_t)i * 3;
    unsigned q[3];
#pragma unroll
    for (int a = 0; a < 3; a++) {
        float mn = fdec(g_mm[b * 6 + a * 2]);
        float mx = fdec(g_mm[b * 6 + a * 2 + 1]);
        float sc = fmaxf(__fsub_rn(mx, mn), 1e-8f);       // clip(max-min, 1e-8)
        float r  = __frcp_rn(sc);
        float nr = __fmul_rn(__fsub_rn(p[a], mn), r);     // (p - pmin) * (1/scale)
        float tq = __fmul_rn(nr, 1023.0f);                // * (RES-1)
        int qi = (int)tq;                                 // trunc toward zero
        qi = max(0, min(qi, 1023));
        q[a] = (unsigned)qi;
    }
    unsigned mort = (expand10(q[0]) << 2) | (expand10(q[1]) << 1) | expand10(q[2]);
    g_keys[i] = ((unsigned long long)(unsigned)b << 47) |
                ((unsigned long long)mort << 17) | (unsigned)n;
}

// ---------------- K4: unpack sort_idx + gather sorted points ----------------
__global__ void __launch_bounds__(256) k_gather(const float* __restrict__ pts,
                                                float* __restrict__ out, int write_idx) {
    int i = blockIdx.x * 256 + threadIdx.x;
    int b = i >> 17;
    unsigned long long k = g_keys_out[i];
    int idx = (int)(k & 0x1FFFFull);
    if (write_idx) out[TOK + CEN + i] = (float)idx;
    const float* s = pts + (((size_t)b << 17) + (size_t)idx) * 3;
    float* d = g_sp + (size_t)i * 3;
    d[0] = s[0]; d[1] = s[1]; d[2] = s[2];
}

// ---------------- K5: centroids ----------------
__global__ void __launch_bounds__(128) k_cent(float* __restrict__ out, int write_cent) {
    int m = blockIdx.x * 128 + threadIdx.x;
    if (m >= BL) return;
    int b = m / LWIN, l = m - b * LWIN;
    const float* sp = g_sp + ((size_t)b * NPTS + (size_t)l * STRIDEW) * 3;
    float sx = 0.f, sy = 0.f, sz = 0.f;
#pragma unroll
    for (int p = 0; p < PATCHW; p++) {
        sx += sp[p * 3 + 0]; sy += sp[p * 3 + 1]; sz += sp[p * 3 + 2];
    }
    float cx = sx / 32.0f, cy = sy / 32.0f, cz = sz / 32.0f;
    g_cent[m * 3 + 0] = cx; g_cent[m * 3 + 1] = cy; g_cent[m * 3 + 2] = cz;
    if (write_cent) {
        out[TOK + m * 3 + 0] = cx; out[TOK + m * 3 + 1] = cy; out[TOK + m * 3 + 2] = cz;
    }
}

// ---------------- K6: per-window MLP + maxpool + pos MLP -> combined(256) ----------------
__global__ void __launch_bounds__(128) k_mlp(const float* __restrict__ W1, const float* __restrict__ b1,
                                             const float* __restrict__ W2, const float* __restrict__ b2,
                                             const float* __restrict__ Wp1, const float* __restrict__ bp1,
                                             const float* __restrict__ Wp2, const float* __restrict__ bp2) {
    __shared__ float locx[32], locy[32], locz[32];
    __shared__ float hp[64];
    __shared__ float c_sm[3];
    __shared__ __align__(16) float h_sm[2048];   // [32 points][64 ch]

    int m = blockIdx.x;
    int t = threadIdx.x;
    int b = m / LWIN, l = m - b * LWIN;

    if (t < 3) c_sm[t] = g_cent[m * 3 + t];
    __syncthreads();

    const float* sp = g_sp + ((size_t)b * NPTS + (size_t)l * STRIDEW) * 3;
    if (t < 32) {
        locx[t] = sp[t * 3 + 0] - c_sm[0];
        locy[t] = sp[t * 3 + 1] - c_sm[1];
        locz[t] = sp[t * 3 + 2] - c_sm[2];
    }
    if (t < 64) {
        float v = fmaf(c_sm[2], Wp1[128 + t],
                  fmaf(c_sm[1], Wp1[64 + t],
                  fmaf(c_sm[0], Wp1[t], bp1[t])));
        hp[t] = fmaxf(v, 0.f);
    }
    __syncthreads();

    // h = relu(local @ W1 + b1) : 32x64, each thread 16 entries
#pragma unroll
    for (int j = 0; j < 16; j++) {
        int i = t + 128 * j;
        int p = i >> 6, d = i & 63;
        float v = fmaf(locz[p], W1[128 + d],
                  fmaf(locy[p], W1[64 + d],
                  fmaf(locx[p], W1[d], b1[d])));
        h_sm[i] = fmaxf(v, 0.f);
    }
    // W2 column for this output channel, packed over channel pairs (f32x2)
    unsigned long long w2p[32];
#pragma unroll
    for (int i = 0; i < 32; i++)
        w2p[i] = pack2(W2[(2 * i) * 128 + t], W2[(2 * i + 1) * 128 + t]);
    __syncthreads();

    float geo = 0.f;                       // feat >= 0, so init 0 == max over relu
    float b2e = b2[t];
    const ulonglong2* hbase = reinterpret_cast<const ulonglong2*>(h_sm);
    for (int p = 0; p < 32; p++) {
        // row of point p = 64 floats = 16 ulonglong2  (FIX: stride 16, not 8)
        const ulonglong2* h2 = hbase + p * 16;
        unsigned long long acc_a = 0ull, acc_b = 0ull;
#pragma unroll
        for (int i = 0; i < 8; i++) {
            ulonglong2 v = h2[i];
            fma2(acc_a, v.x, w2p[2 * i + 0], acc_a);
            fma2(acc_b, v.y, w2p[2 * i + 1], acc_b);
        }
        const ulonglong2* h2b = h2 + 8;
#pragma unroll
        for (int i = 0; i < 8; i++) {
            ulonglong2 v = h2b[i];
            fma2(acc_a, v.x, w2p[16 + 2 * i + 0], acc_a);
            fma2(acc_b, v.y, w2p[16 + 2 * i + 1], acc_b);
        }
        float2 f = unpack2(add2(acc_a, acc_b));
        geo = fmaxf(geo, f.x + f.y + b2e);
    }
    float pos = bp2[t];
#pragma unroll
    for (int d = 0; d < 64; d++) pos = fmaf(hp[d], Wp2[d * 128 + t], pos);

    size_t o = (size_t)m * 256 + t;
    g_comb[o]       = geo;
    g_comb[o + 128] = pos;
}

// ---------------- K7: tokens = combined(65528x256) @ Wproj(256x256) + bproj ----------------
// k-packed f32x2 GEMM: A and B tiles stored k-contiguous; both operands load as
// natural 64-bit k-pairs; accumulators hold packed even/odd-k partial sums.
__global__ void __launch_bounds__(256) k_proj(const float* __restrict__ Wp,
                                              const float* __restrict__ bp,
                                              float* __restrict__ out) {
    __shared__ __align__(16) float a_t[64][36];  // [row][kk], stride 36
    __shared__ __align__(16) float b_t[64][36];  // [col][kk], stride 36
    int row0 = blockIdx.x * 64, col0 = blockIdx.y * 64;
    int t = threadIdx.x;
    int tr = t >> 4, tc = t & 15;
    int r0 = tr * 4;                              // rows r0..r0+3
    // columns handled by this thread: tc + 16*j, j=0..3
    unsigned long long acc2[4][4] = {};           // [row i][col j], packed over (k even, k odd)

    for (int k0 = 0; k0 < 256; k0 += 32) {
        // fill A: thread loads float4 of g_comb row, stores k-contiguous
        int kk4 = (t & 7) * 4;
        int r = t >> 3;
#pragma unroll
        for (int pass = 0; pass < 2; pass++) {
            int rr = r + 32 * pass;
            int grow = row0 + rr;
            float4 v = make_float4(0.f, 0.f, 0.f, 0.f);
            if (grow < BL)
                v = *reinterpret_cast<const float4*>(g_comb + (size_t)grow * 256 + k0 + kk4);
            *reinterpret_cast<float4*>(&a_t[rr][kk4]) = v;
        }
        // fill B transposed: b_t[col][kk] = Wp[(k0+kk)*256 + col0+col]
#pragma unroll
        for (int j = 0; j < 8; j++) {
            int kk = (t >> 6) + 4 * j;
            int o = t & 63;
            b_t[o][kk] = Wp[(k0 + kk) * 256 + col0 + o];
        }
        __syncthreads();

#pragma unroll
        for (int kk2 = 0; kk2 < 16; kk2 += 2) {
            // a pairs for 4 rows, 2 kk2 steps at once (16B aligned since kk2 even)
            ulonglong2 av[4];
#pragma unroll
            for (int i = 0; i < 4; i++)
                av[i] = *reinterpret_cast<const ulonglong2*>(&a_t[r0 + i][2 * kk2]);
            ulonglong2 bv[4];
#pragma unroll
            for (int j = 0; j < 4; j++)
                bv[j] = *reinterpret_cast<const ulonglong2*>(&b_t[tc + 16 * j][2 * kk2]);
#pragma unroll
            for (int i = 0; i < 4; i++)
#pragma unroll
                for (int j = 0; j < 4; j++) {
                    fma2(acc2[i][j], av[i].x, bv[j].x, acc2[i][j]);
                    fma2(acc2[i][j], av[i].y, bv[j].y, acc2[i][j]);
                }
        }
        __syncthreads();
    }
#pragma unroll
    for (int i = 0; i < 4; i++) {
        int row = row0 + r0 + i;
        if (row < BL) {
#pragma unroll
            for (int j = 0; j < 4; j++) {
                int col = col0 + tc + 16 * j;
                float2 f = unpack2(acc2[i][j]);
                out[(size_t)row * 256 + col] = f.x + f.y + bp[col];
            }
        }
    }
}

// ---------------- launch ----------------
extern "C" void kernel_launch(void* const* d_in, const int* in_sizes, int n_in,
                              void* d_out, int out_size) {
    const float* points = (const float*)d_in[0];
    const float* W1   = (const float*)d_in[1];
    const float* b1   = (const float*)d_in[2];
    const float* W2   = (const float*)d_in[3];
    const float* b2   = (const float*)d_in[4];
    const float* Wp1  = (const float*)d_in[5];
    const float* bp1  = (const float*)d_in[6];
    const float* Wp2  = (const float*)d_in[7];
    const float* bp2  = (const float*)d_in[8];
    const float* Wproj = (const float*)d_in[9];
    const float* bproj = (const float*)d_in[10];
    float* out = (float*)d_out;

    int write_cent = (out_size >= TOK + CEN) ? 1 : 0;
    int write_idx  = (out_size >= TOK + CEN + IDXN) ? 1 : 0;

    k_reset<<<1, 64>>>();
    k_minmax<<<BATCH * 64, 256>>>(points);
    k_keys<<<BN / 256, 256>>>(points);

    void* d_temp = nullptr;
    unsigned long long* kin = nullptr;
    unsigned long long* kout = nullptr;
    cudaGetSymbolAddress(&d_temp, g_temp);
    cudaGetSymbolAddress((void**)&kin, g_keys);
    cudaGetSymbolAddress((void**)&kout, g_keys_out);

    size_t temp_bytes = 0;
    cub::DeviceRadixSort::SortKeys(nullptr, temp_bytes, kin, kout, BN, 0, 50);
    if (temp_bytes <= sizeof(g_temp)) {
        cub::DeviceRadixSort::SortKeys(d_temp, temp_bytes, kin, kout, BN, 0, 50);
    }

    k_gather<<<BN / 256, 256>>>(points, out, write_idx);
    k_cent<<<(BL + 127) / 128, 128>>>(out, write_cent);
    k_mlp<<<BL, 128>>>(W1, b1, W2, b2, Wp1, bp1, Wp2, bp2);
    k_proj<<<dim3((BL + 63) / 64, 4), 256>>>(Wproj, bproj, out);
}

// round 6
// speedup vs baseline: 2.3525x; 2.3210x over previous
#include <cuda_runtime.h>
#include <cuda_bf16.h>
#include <cub/cub.cuh>
#include <cstdint>

// ---------------- problem constants ----------------
#define BATCH   8
#define NPTS    131072
#define PATCHW  32
#define STRIDEW 16
#define LWIN    8191                    // (131072-32)/16 + 1
#define BL      (BATCH*LWIN)            // 65528
#define BN      (BATCH*NPTS)            // 1048576
#define TOK     (BL*256)                // tokens elems
#define CEN     (BL*3)                  // centroid elems
#define IDXN    BN                      // sort_idx elems
#define COMBK   192                     // [geo(128) | hp(64)]

// ---------------- static device scratch ----------------
__device__ __align__(256) unsigned long long g_keys[BN];
__device__ __align__(256) unsigned long long g_keys_out[BN];
__device__ __align__(256) unsigned char      g_temp[128u * 1024u * 1024u];
__device__ unsigned                          g_mm[48];
__device__ __align__(16) float               g_sp[BN * 3];
__device__ float                             g_cent[BL * 3];
__device__ __align__(16) float               g_comb[(size_t)BL * COMBK];
__device__ __align__(16) float               g_wcat[192 * 256];
__device__ __align__(16) float               g_bfold[256];

// ---------------- f32x2 packed helpers (k_proj) ----------------
__device__ __forceinline__ float2 unpack2(unsigned long long v) {
    float2 r;
    asm("mov.b64 {%0, %1}, %2;" : "=f"(r.x), "=f"(r.y) : "l"(v));
    return r;
}
__device__ __forceinline__ void fma2(unsigned long long& d, unsigned long long a,
                                     unsigned long long b, unsigned long long c) {
    asm("fma.rn.f32x2 %0, %1, %2, %3;" : "=l"(d) : "l"(a), "l"(b), "l"(c));
}

// ---------------- mma.sync helpers (sm_80+ PTX, no 'a' target needed) ----------------
__device__ __forceinline__ uint32_t smem_u32(const void* p) {
    uint32_t a;
    asm("{ .reg .u64 t; cvta.to.shared.u64 t, %1; cvt.u32.u64 %0, t; }" : "=r"(a) : "l"(p));
    return a;
}
__device__ __forceinline__ void ldsm4(uint32_t* r, uint32_t addr) {
    asm volatile("ldmatrix.sync.aligned.m8n8.x4.shared.b16 {%0,%1,%2,%3}, [%4];"
        : "=r"(r[0]), "=r"(r[1]), "=r"(r[2]), "=r"(r[3]) : "r"(addr));
}
__device__ __forceinline__ void ldsm2t(uint32_t* r, uint32_t addr) {
    asm volatile("ldmatrix.sync.aligned.m8n8.x2.trans.shared.b16 {%0,%1}, [%2];"
        : "=r"(r[0]), "=r"(r[1]) : "r"(addr));
}
__device__ __forceinline__ void mma_bf16(float* d, const uint32_t* a, const uint32_t* b) {
    asm volatile("mma.sync.aligned.m16n8k16.row.col.f32.bf16.bf16.f32 "
        "{%0,%1,%2,%3}, {%4,%5,%6,%7}, {%8,%9}, {%0,%1,%2,%3};"
        : "+f"(d[0]), "+f"(d[1]), "+f"(d[2]), "+f"(d[3])
        : "r"(a[0]), "r"(a[1]), "r"(a[2]), "r"(a[3]), "r"(b[0]), "r"(b[1]));
}

// ---------------- misc helpers ----------------
__device__ __forceinline__ unsigned fenc(float f) {
    unsigned u = __float_as_uint(f);
    return (u & 0x80000000u) ? ~u : (u | 0x80000000u);
}
__device__ __forceinline__ float fdec(unsigned u) {
    return (u & 0x80000000u) ? __uint_as_float(u ^ 0x80000000u) : __uint_as_float(~u);
}
__device__ __forceinline__ unsigned expand10(unsigned v) {
    v &= 0x3FFu;
    v = (v | (v << 16)) & 0x030000FFu;
    v = (v | (v << 8))  & 0x0300F00Fu;
    v = (v | (v << 4))  & 0x030C30C3u;
    v = (v | (v << 2))  & 0x09249249u;
    return v;
}

// ---------------- K: weight fold (independent of data path) ----------------
// g_wcat rows 0-127 = Wproj[0:128]; rows 128-191 = Wp2 @ Wproj[128:256]
// g_bfold = bproj + bp2 @ Wproj[128:256]
__global__ void __launch_bounds__(256) k_fold(const float* __restrict__ Wproj,
                                              const float* __restrict__ Wp2,
                                              const float* __restrict__ bp2,
                                              const float* __restrict__ bproj) {
    int r = blockIdx.x, c = threadIdx.x;
    if (r < 128) {
        g_wcat[r * 256 + c] = Wproj[r * 256 + c];
    } else if (r < 192) {
        int d = r - 128;
        float s = 0.f;
        for (int j = 0; j < 128; j++)
            s = fmaf(Wp2[d * 128 + j], Wproj[(128 + j) * 256 + c], s);
        g_wcat[r * 256 + c] = s;
    } else {
        float s = bproj[c];
        for (int d = 0; d < 128; d++)
            s = fmaf(bp2[d], Wproj[(128 + d) * 256 + c], s);
        g_bfold[c] = s;
    }
}

// ---------------- K0/K1/K2 ----------------
__global__ void k_reset() {
    int t = threadIdx.x;
    if (t < 48) g_mm[t] = (t & 1) ? 0u : 0xFFFFFFFFu;
}

__global__ void __launch_bounds__(256) k_minmax(const float* __restrict__ pts) {
    int b = blockIdx.x >> 6, chunk = blockIdx.x & 63, t = threadIdx.x;
    unsigned mn0 = ~0u, mn1 = ~0u, mn2 = ~0u, mx0 = 0u, mx1 = 0u, mx2 = 0u;
    size_t base = (size_t)b * NPTS + (size_t)chunk * 2048;
    for (int j = t; j < 2048; j += 256) {
        const float* p = pts + (base + j) * 3;
        unsigned e0 = fenc(p[0]), e1 = fenc(p[1]), e2 = fenc(p[2]);
        mn0 = min(mn0, e0); mx0 = max(mx0, e0);
        mn1 = min(mn1, e1); mx1 = max(mx1, e1);
        mn2 = min(mn2, e2); mx2 = max(mx2, e2);
    }
    mn0 = __reduce_min_sync(0xffffffffu, mn0); mx0 = __reduce_max_sync(0xffffffffu, mx0);
    mn1 = __reduce_min_sync(0xffffffffu, mn1); mx1 = __reduce_max_sync(0xffffffffu, mx1);
    mn2 = __reduce_min_sync(0xffffffffu, mn2); mx2 = __reduce_max_sync(0xffffffffu, mx2);
    __shared__ unsigned s[6];
    if (t < 6) s[t] = (t < 3) ? 0xFFFFFFFFu : 0u;
    __syncthreads();
    if ((t & 31) == 0) {
        atomicMin(&s[0], mn0); atomicMin(&s[1], mn1); atomicMin(&s[2], mn2);
        atomicMax(&s[3], mx0); atomicMax(&s[4], mx1); atomicMax(&s[5], mx2);
    }
    __syncthreads();
    if (t < 3)      atomicMin(&g_mm[b * 6 + t * 2], s[t]);
    else if (t < 6) atomicMax(&g_mm[b * 6 + (t - 3) * 2 + 1], s[t]);
}

__global__ void __launch_bounds__(256) k_keys(const float* __restrict__ pts) {
    int i = blockIdx.x * 256 + threadIdx.x;
    int b = i >> 17;
    int n = i & (NPTS - 1);
    const float* p = pts + (size_t)i * 3;
    unsigned q[3];
#pragma unroll
    for (int a = 0; a < 3; a++) {
        float mn = fdec(g_mm[b * 6 + a * 2]);
        float mx = fdec(g_mm[b * 6 + a * 2 + 1]);
        float sc = fmaxf(__fsub_rn(mx, mn), 1e-8f);
        float r  = __frcp_rn(sc);
        float nr = __fmul_rn(__fsub_rn(p[a], mn), r);
        float tq = __fmul_rn(nr, 1023.0f);
        int qi = (int)tq;
        qi = max(0, min(qi, 1023));
        q[a] = (unsigned)qi;
    }
    unsigned mort = (expand10(q[0]) << 2) | (expand10(q[1]) << 1) | expand10(q[2]);
    g_keys[i] = ((unsigned long long)(unsigned)b << 47) |
                ((unsigned long long)mort << 17) | (unsigned)n;
}

// ---------------- K4: sort_idx + gather ----------------
__global__ void __launch_bounds__(256) k_gather(const float* __restrict__ pts,
                                                float* __restrict__ out, int write_idx) {
    int i = blockIdx.x * 256 + threadIdx.x;
    int b = i >> 17;
    unsigned long long k = g_keys_out[i];
    int idx = (int)(k & 0x1FFFFull);
    if (write_idx) out[TOK + CEN + i] = (float)idx;
    const float* s = pts + (((size_t)b << 17) + (size_t)idx) * 3;
    float* d = g_sp + (size_t)i * 3;
    d[0] = s[0]; d[1] = s[1]; d[2] = s[2];
}

// ---------------- K5: centroids ----------------
__global__ void __launch_bounds__(128) k_cent(float* __restrict__ out, int write_cent) {
    int m = blockIdx.x * 128 + threadIdx.x;
    if (m >= BL) return;
    int b = m / LWIN, l = m - b * LWIN;
    const float* sp = g_sp + ((size_t)b * NPTS + (size_t)l * STRIDEW) * 3;
    float sx = 0.f, sy = 0.f, sz = 0.f;
#pragma unroll
    for (int p = 0; p < PATCHW; p++) {
        sx += sp[p * 3 + 0]; sy += sp[p * 3 + 1]; sz += sp[p * 3 + 2];
    }
    float cx = sx / 32.0f, cy = sy / 32.0f, cz = sz / 32.0f;
    g_cent[m * 3 + 0] = cx; g_cent[m * 3 + 1] = cy; g_cent[m * 3 + 2] = cz;
    if (write_cent) {
        out[TOK + m * 3 + 0] = cx; out[TOK + m * 3 + 1] = cy; out[TOK + m * 3 + 2] = cz;
    }
}

// ---------------- K_hp: hp = relu(cent @ Wp1 + bp1) -> g_comb[:,128:192] ----------------
__global__ void __launch_bounds__(128) k_hp(const float* __restrict__ Wp1,
                                            const float* __restrict__ bp1) {
    int t = threadIdx.x;
    int m = blockIdx.x * 2 + (t >> 6);
    int ch = t & 63;
    if (m >= BL) return;
    float cx = g_cent[m * 3 + 0], cy = g_cent[m * 3 + 1], cz = g_cent[m * 3 + 2];
    float v = fmaf(cz, Wp1[128 + ch], fmaf(cy, Wp1[64 + ch], fmaf(cx, Wp1[ch], bp1[ch])));
    g_comb[(size_t)m * COMBK + 128 + ch] = fmaxf(v, 0.f);
}

// ---------------- K_geo: mma.sync bf16-split GEMM + maxpool ----------------
// Per window: D[32p x 128c] = h[32x64] @ W2[64x128], h/W2 split hi+mid bf16,
// 3 cross-products (HH, HM, MH). Maxpool over 32 points in-register.
#define GW    16        // windows per block
#define HSTR  72        // bf16 per h row (padded: 144B, 16B bank phase shift)
#define WSTR  136       // bf16 per W2 row (padded: 272B)

__global__ void __launch_bounds__(128) k_geo(const float* __restrict__ W1,
                                             const float* __restrict__ b1,
                                             const float* __restrict__ W2,
                                             const float* __restrict__ b2) {
    __shared__ __align__(16) __nv_bfloat16 w2hi_s[64 * WSTR];
    __shared__ __align__(16) __nv_bfloat16 w2mid_s[64 * WSTR];
    __shared__ __align__(16) __nv_bfloat16 hhi_s[32 * HSTR];
    __shared__ __align__(16) __nv_bfloat16 hmid_s[32 * HSTR];
    __shared__ float W1s[192], b1s[64], b2s[128];

    int t = threadIdx.x, wi = t >> 5, lane = t & 31;

    if (t < 64) {
        W1s[t] = W1[t]; W1s[64 + t] = W1[64 + t]; W1s[128 + t] = W1[128 + t];
        b1s[t] = b1[t];
    }
    b2s[t] = b2[t];
    // W2 split (once per block)
    for (int i = t; i < 8192; i += 128) {
        int k = i >> 7, c = i & 127;
        float v = W2[i];
        __nv_bfloat16 hi = __float2bfloat16_rn(v);
        __nv_bfloat16 mid = __float2bfloat16_rn(v - __bfloat162float(hi));
        w2hi_s[k * WSTR + c]  = hi;
        w2mid_s[k * WSTR + c] = mid;
    }
    __syncthreads();

    uint32_t hhi_b = smem_u32(hhi_s), hmid_b = smem_u32(hmid_s);
    uint32_t w2hi_b = smem_u32(w2hi_s), w2mid_b = smem_u32(w2mid_s);

    int p  = t & 31;            // point owned for h build
    int kb = (t >> 5) * 16;     // k range owned for h build

    // ldmatrix address components (lane-dependent)
    uint32_t aoff = (uint32_t)(lane & 15) * (HSTR * 2) + (uint32_t)((lane >> 4) & 1) * 16;
    uint32_t boff = (uint32_t)(lane & 15) * (WSTR * 2) + (uint32_t)(wi * 32) * 2;

    for (int w = 0; w < GW; w++) {
        int mi = blockIdx.x * GW + w;
        int m  = min(mi, BL - 1);
        int b  = m / LWIN, l = m - b * LWIN;

        // ---- build h (bf16 hi/mid) for (p, kb..kb+15) ----
        {
            const float* sp = g_sp + ((size_t)b * NPTS + (size_t)l * STRIDEW + p) * 3;
            float lx = sp[0] - g_cent[m * 3 + 0];
            float ly = sp[1] - g_cent[m * 3 + 1];
            float lz = sp[2] - g_cent[m * 3 + 2];
#pragma unroll
            for (int j = 0; j < 16; j += 2) {
                int k = kb + j;
                float v0 = fmaxf(fmaf(lz, W1s[128 + k],
                           fmaf(ly, W1s[64 + k], fmaf(lx, W1s[k], b1s[k]))), 0.f);
                float v1 = fmaxf(fmaf(lz, W1s[128 + k + 1],
                           fmaf(ly, W1s[64 + k + 1], fmaf(lx, W1s[k + 1], b1s[k + 1]))), 0.f);
                uint32_t h2;
                asm("cvt.rn.bf16x2.f32 %0, %1, %2;" : "=r"(h2) : "f"(v1), "f"(v0));
                float h0f = __uint_as_float(h2 << 16);
                float h1f = __uint_as_float(h2 & 0xFFFF0000u);
                uint32_t m2;
                asm("cvt.rn.bf16x2.f32 %0, %1, %2;" : "=r"(m2) : "f"(v1 - h1f), "f"(v0 - h0f));
                *(uint32_t*)&hhi_s[p * HSTR + k]  = h2;
                *(uint32_t*)&hmid_s[p * HSTR + k] = m2;
            }
        }
        __syncthreads();

        // ---- GEMM: 2 m-tiles x 4 n-tiles x 4 k-tiles x 3 splits ----
        float acc[2][4][4] = {};
#pragma unroll
        for (int kt = 0; kt < 4; kt++) {
            uint32_t aH[2][4], aM[2][4];
            uint32_t ak = (uint32_t)(kt * 32);  // kt*16 bf16 = 32B
            ldsm4(aH[0], hhi_b  + aoff + ak);
            ldsm4(aH[1], hhi_b  + aoff + ak + 16 * (HSTR * 2));
            ldsm4(aM[0], hmid_b + aoff + ak);
            ldsm4(aM[1], hmid_b + aoff + ak + 16 * (HSTR * 2));
            uint32_t bk = (uint32_t)(kt * 16) * (WSTR * 2);
#pragma unroll
            for (int nt = 0; nt < 4; nt++) {
                uint32_t bH[2], bM[2];
                uint32_t bn = (uint32_t)(nt * 16);  // nt*8 bf16 = 16B
                ldsm2t(bH, w2hi_b  + boff + bk + bn);
                ldsm2t(bM, w2mid_b + boff + bk + bn);
#pragma unroll
                for (int mt = 0; mt < 2; mt++) {
                    mma_bf16(acc[mt][nt], aH[mt], bH);
                    mma_bf16(acc[mt][nt], aH[mt], bM);
                    mma_bf16(acc[mt][nt], aM[mt], bH);
                }
            }
        }

        // ---- epilogue: maxpool over 32 points, +b2, relu ----
        if (mi < BL) {
#pragma unroll
            for (int nt = 0; nt < 4; nt++) {
                float m0 = fmaxf(fmaxf(acc[0][nt][0], acc[0][nt][2]),
                                 fmaxf(acc[1][nt][0], acc[1][nt][2]));
                float m1 = fmaxf(fmaxf(acc[0][nt][1], acc[0][nt][3]),
                                 fmaxf(acc[1][nt][1], acc[1][nt][3]));
#pragma unroll
                for (int s = 4; s <= 16; s <<= 1) {
                    m0 = fmaxf(m0, __shfl_xor_sync(0xffffffffu, m0, s));
                    m1 = fmaxf(m1, __shfl_xor_sync(0xffffffffu, m1, s));
                }
                if (lane < 4) {
                    int c = wi * 32 + nt * 8 + 2 * lane;
                    g_comb[(size_t)mi * COMBK + c]     = fmaxf(m0 + b2s[c], 0.f);
                    g_comb[(size_t)mi * COMBK + c + 1] = fmaxf(m1 + b2s[c + 1], 0.f);
                }
            }
        }
        __syncthreads();
    }
}

// ---------------- K7: tokens = comb(BLx192) @ g_wcat(192x256) + g_bfold ----------------
__global__ void __launch_bounds__(256) k_proj(float* __restrict__ out) {
    __shared__ __align__(16) float a_t[64][36];
    __shared__ __align__(16) float b_t[64][36];
    int row0 = blockIdx.x * 64, col0 = blockIdx.y * 64;
    int t = threadIdx.x;
    int tr = t >> 4, tc = t & 15;
    int r0 = tr * 4;
    unsigned long long acc2[4][4] = {};

    for (int k0 = 0; k0 < COMBK; k0 += 32) {
        int kk4 = (t & 7) * 4;
        int r = t >> 3;
#pragma unroll
        for (int pass = 0; pass < 2; pass++) {
            int rr = r + 32 * pass;
            int grow = row0 + rr;
            float4 v = make_float4(0.f, 0.f, 0.f, 0.f);
            if (grow < BL)
                v = *reinterpret_cast<const float4*>(g_comb + (size_t)grow * COMBK + k0 + kk4);
            *reinterpret_cast<float4*>(&a_t[rr][kk4]) = v;
        }
#pragma unroll
        for (int j = 0; j < 8; j++) {
            int kk = (t >> 6) + 4 * j;
            int o = t & 63;
            b_t[o][kk] = g_wcat[(k0 + kk) * 256 + col0 + o];
        }
        __syncthreads();
#pragma unroll
        for (int kk2 = 0; kk2 < 16; kk2 += 2) {
            ulonglong2 av[4];
#pragma unroll
            for (int i = 0; i < 4; i++)
                av[i] = *reinterpret_cast<const ulonglong2*>(&a_t[r0 + i][2 * kk2]);
            ulonglong2 bv[4];
#pragma unroll
            for (int j = 0; j < 4; j++)
                bv[j] = *reinterpret_cast<const ulonglong2*>(&b_t[tc + 16 * j][2 * kk2]);
#pragma unroll
            for (int i = 0; i < 4; i++)
#pragma unroll
                for (int j = 0; j < 4; j++) {
                    fma2(acc2[i][j], av[i].x, bv[j].x, acc2[i][j]);
                    fma2(acc2[i][j], av[i].y, bv[j].y, acc2[i][j]);
                }
        }
        __syncthreads();
    }
#pragma unroll
    for (int i = 0; i < 4; i++) {
        int row = row0 + r0 + i;
        if (row < BL) {
#pragma unroll
            for (int j = 0; j < 4; j++) {
                int col = col0 + tc + 16 * j;
                float2 f = unpack2(acc2[i][j]);
                out[(size_t)row * 256 + col] = f.x + f.y + g_bfold[col];
            }
        }
    }
}

// ---------------- launch ----------------
extern "C" void kernel_launch(void* const* d_in, const int* in_sizes, int n_in,
                              void* d_out, int out_size) {
    const float* points = (const float*)d_in[0];
    const float* W1   = (const float*)d_in[1];
    const float* b1   = (const float*)d_in[2];
    const float* W2   = (const float*)d_in[3];
    const float* b2   = (const float*)d_in[4];
    const float* Wp1  = (const float*)d_in[5];
    const float* bp1  = (const float*)d_in[6];
    const float* Wp2  = (const float*)d_in[7];
    const float* bp2  = (const float*)d_in[8];
    const float* Wproj = (const float*)d_in[9];
    const float* bproj = (const float*)d_in[10];
    float* out = (float*)d_out;

    int write_cent = (out_size >= TOK + CEN) ? 1 : 0;
    int write_idx  = (out_size >= TOK + CEN + IDXN) ? 1 : 0;

    k_fold<<<193, 256>>>(Wproj, Wp2, bp2, bproj);
    k_reset<<<1, 64>>>();
    k_minmax<<<BATCH * 64, 256>>>(points);
    k_keys<<<BN / 256, 256>>>(points);

    void* d_temp = nullptr;
    unsigned long long* kin = nullptr;
    unsigned long long* kout = nullptr;
    cudaGetSymbolAddress(&d_temp, g_temp);
    cudaGetSymbolAddress((void**)&kin, g_keys);
    cudaGetSymbolAddress((void**)&kout, g_keys_out);

    size_t temp_bytes = 0;
    cub::DeviceRadixSort::SortKeys(nullptr, temp_bytes, kin, kout, BN, 0, 50);
    if (temp_bytes <= sizeof(g_temp)) {
        cub::DeviceRadixSort::SortKeys(d_temp, temp_bytes, kin, kout, BN, 0, 50);
    }

    k_gather<<<BN / 256, 256>>>(points, out, write_idx);
    k_cent<<<(BL + 127) / 128, 128>>>(out, write_cent);
    k_hp<<<(BL + 1) / 2, 128>>>(Wp1, bp1);
    k_geo<<<(BL + GW - 1) / GW, 128>>>(W1, b1, W2, b2);
    k_proj<<<dim3((BL + 63) / 64, 4), 256>>>(out);
}

// round 7
// speedup vs baseline: 2.8973x; 1.2316x over previous
#include <cuda_runtime.h>
#include <cuda_bf16.h>
#include <cub/cub.cuh>
#include <cstdint>

// ---------------- problem constants ----------------
#define BATCH   8
#define NPTS    131072
#define PATCHW  32
#define STRIDEW 16
#define LWIN    8191                    // (131072-32)/16 + 1
#define BL      (BATCH*LWIN)            // 65528
#define BLP     65536                   // padded rows for tile overrun
#define BN      (BATCH*NPTS)            // 1048576
#define TOK     (BL*256)                // tokens elems
#define CEN     (BL*3)                  // centroid elems
#define IDXN    BN                      // sort_idx elems
#define COMBK   192                     // [geo(128) | hp(64)]

// ---------------- static device scratch ----------------
__device__ __align__(256) unsigned long long g_keys[BN];
__device__ __align__(256) unsigned long long g_keys_out[BN];
__device__ __align__(256) unsigned char      g_temp[128u * 1024u * 1024u];
__device__ unsigned                          g_mm[48];
__device__ __align__(16) float               g_sp[BN * 3];
__device__ float                             g_cent[BL * 3];
__device__ __align__(16) __nv_bfloat16       g_comb_hi[(size_t)BLP * COMBK];   // zero-init
__device__ __align__(16) __nv_bfloat16       g_comb_mid[(size_t)BLP * COMBK];  // zero-init
__device__ __align__(16) __nv_bfloat16       g_wb_hi[192 * 256];
__device__ __align__(16) __nv_bfloat16       g_wb_mid[192 * 256];
__device__ __align__(16) float               g_bfold[256];

// ---------------- mma.sync helpers (sm_80+ PTX) ----------------
__device__ __forceinline__ uint32_t smem_u32(const void* p) {
    uint32_t a;
    asm("{ .reg .u64 t; cvta.to.shared.u64 t, %1; cvt.u32.u64 %0, t; }" : "=r"(a) : "l"(p));
    return a;
}
__device__ __forceinline__ void ldsm4(uint32_t* r, uint32_t addr) {
    asm volatile("ldmatrix.sync.aligned.m8n8.x4.shared.b16 {%0,%1,%2,%3}, [%4];"
        : "=r"(r[0]), "=r"(r[1]), "=r"(r[2]), "=r"(r[3]) : "r"(addr));
}
__device__ __forceinline__ void ldsm2t(uint32_t* r, uint32_t addr) {
    asm volatile("ldmatrix.sync.aligned.m8n8.x2.trans.shared.b16 {%0,%1}, [%2];"
        : "=r"(r[0]), "=r"(r[1]) : "r"(addr));
}
__device__ __forceinline__ void mma_bf16(float* d, const uint32_t* a, const uint32_t* b) {
    asm volatile("mma.sync.aligned.m16n8k16.row.col.f32.bf16.bf16.f32 "
        "{%0,%1,%2,%3}, {%4,%5,%6,%7}, {%8,%9}, {%0,%1,%2,%3};"
        : "+f"(d[0]), "+f"(d[1]), "+f"(d[2]), "+f"(d[3])
        : "r"(a[0]), "r"(a[1]), "r"(a[2]), "r"(a[3]), "r"(b[0]), "r"(b[1]));
}
__device__ __forceinline__ void bf16split(float v, __nv_bfloat16& hi, __nv_bfloat16& mid) {
    hi = __float2bfloat16_rn(v);
    mid = __float2bfloat16_rn(v - __bfloat162float(hi));
}

// ---------------- misc helpers ----------------
__device__ __forceinline__ unsigned fenc(float f) {
    unsigned u = __float_as_uint(f);
    return (u & 0x80000000u) ? ~u : (u | 0x80000000u);
}
__device__ __forceinline__ float fdec(unsigned u) {
    return (u & 0x80000000u) ? __uint_as_float(u ^ 0x80000000u) : __uint_as_float(~u);
}
__device__ __forceinline__ unsigned expand10(unsigned v) {
    v &= 0x3FFu;
    v = (v | (v << 16)) & 0x030000FFu;
    v = (v | (v << 8))  & 0x0300F00Fu;
    v = (v | (v << 4))  & 0x030C30C3u;
    v = (v | (v << 2))  & 0x09249249u;
    return v;
}

// ---------------- K: weight fold -> bf16 split ----------------
// rows 0-127 = Wproj[0:128]; rows 128-191 = Wp2 @ Wproj[128:256]; bias fold.
__global__ void __launch_bounds__(256) k_fold(const float* __restrict__ Wproj,
                                              const float* __restrict__ Wp2,
                                              const float* __restrict__ bp2,
                                              const float* __restrict__ bproj) {
    int r = blockIdx.x, c = threadIdx.x;
    if (r < 128) {
        __nv_bfloat16 hi, mid;
        bf16split(Wproj[r * 256 + c], hi, mid);
        g_wb_hi[r * 256 + c] = hi; g_wb_mid[r * 256 + c] = mid;
    } else if (r < 192) {
        int d = r - 128;
        float s = 0.f;
        for (int j = 0; j < 128; j++)
            s = fmaf(Wp2[d * 128 + j], Wproj[(128 + j) * 256 + c], s);
        __nv_bfloat16 hi, mid;
        bf16split(s, hi, mid);
        g_wb_hi[r * 256 + c] = hi; g_wb_mid[r * 256 + c] = mid;
    } else {
        float s = bproj[c];
        for (int d = 0; d < 128; d++)
            s = fmaf(bp2[d], Wproj[(128 + d) * 256 + c], s);
        g_bfold[c] = s;
    }
}

// ---------------- K0/K1/K2 ----------------
__global__ void k_reset() {
    int t = threadIdx.x;
    if (t < 48) g_mm[t] = (t & 1) ? 0u : 0xFFFFFFFFu;
}

__global__ void __launch_bounds__(256) k_minmax(const float* __restrict__ pts) {
    int b = blockIdx.x >> 6, chunk = blockIdx.x & 63, t = threadIdx.x;
    unsigned mn0 = ~0u, mn1 = ~0u, mn2 = ~0u, mx0 = 0u, mx1 = 0u, mx2 = 0u;
    size_t base = (size_t)b * NPTS + (size_t)chunk * 2048;
    for (int j = t; j < 2048; j += 256) {
        const float* p = pts + (base + j) * 3;
        unsigned e0 = fenc(p[0]), e1 = fenc(p[1]), e2 = fenc(p[2]);
        mn0 = min(mn0, e0); mx0 = max(mx0, e0);
        mn1 = min(mn1, e1); mx1 = max(mx1, e1);
        mn2 = min(mn2, e2); mx2 = max(mx2, e2);
    }
    mn0 = __reduce_min_sync(0xffffffffu, mn0); mx0 = __reduce_max_sync(0xffffffffu, mx0);
    mn1 = __reduce_min_sync(0xffffffffu, mn1); mx1 = __reduce_max_sync(0xffffffffu, mx1);
    mn2 = __reduce_min_sync(0xffffffffu, mn2); mx2 = __reduce_max_sync(0xffffffffu, mx2);
    __shared__ unsigned s[6];
    if (t < 6) s[t] = (t < 3) ? 0xFFFFFFFFu : 0u;
    __syncthreads();
    if ((t & 31) == 0) {
        atomicMin(&s[0], mn0); atomicMin(&s[1], mn1); atomicMin(&s[2], mn2);
        atomicMax(&s[3], mx0); atomicMax(&s[4], mx1); atomicMax(&s[5], mx2);
    }
    __syncthreads();
    if (t < 3)      atomicMin(&g_mm[b * 6 + t * 2], s[t]);
    else if (t < 6) atomicMax(&g_mm[b * 6 + (t - 3) * 2 + 1], s[t]);
}

__global__ void __launch_bounds__(256) k_keys(const float* __restrict__ pts) {
    int i = blockIdx.x * 256 + threadIdx.x;
    int b = i >> 17;
    int n = i & (NPTS - 1);
    const float* p = pts + (size_t)i * 3;
    unsigned q[3];
#pragma unroll
    for (int a = 0; a < 3; a++) {
        float mn = fdec(g_mm[b * 6 + a * 2]);
        float mx = fdec(g_mm[b * 6 + a * 2 + 1]);
        float sc = fmaxf(__fsub_rn(mx, mn), 1e-8f);
        float r  = __frcp_rn(sc);
        float nr = __fmul_rn(__fsub_rn(p[a], mn), r);
        float tq = __fmul_rn(nr, 1023.0f);
        int qi = (int)tq;
        qi = max(0, min(qi, 1023));
        q[a] = (unsigned)qi;
    }
    unsigned mort = (expand10(q[0]) << 2) | (expand10(q[1]) << 1) | expand10(q[2]);
    g_keys[i] = ((unsigned long long)(unsigned)b << 47) |
                ((unsigned long long)mort << 17) | (unsigned)n;
}

// ---------------- K4: sort_idx + gather ----------------
__global__ void __launch_bounds__(256) k_gather(const float* __restrict__ pts,
                                                float* __restrict__ out, int write_idx) {
    int i = blockIdx.x * 256 + threadIdx.x;
    int b = i >> 17;
    unsigned long long k = g_keys_out[i];
    int idx = (int)(k & 0x1FFFFull);
    if (write_idx) out[TOK + CEN + i] = (float)idx;
    const float* s = pts + (((size_t)b << 17) + (size_t)idx) * 3;
    float* d = g_sp + (size_t)i * 3;
    d[0] = s[0]; d[1] = s[1]; d[2] = s[2];
}

// ---------------- K5: centroids ----------------
__global__ void __launch_bounds__(128) k_cent(float* __restrict__ out, int write_cent) {
    int m = blockIdx.x * 128 + threadIdx.x;
    if (m >= BL) return;
    int b = m / LWIN, l = m - b * LWIN;
    const float* sp = g_sp + ((size_t)b * NPTS + (size_t)l * STRIDEW) * 3;
    float sx = 0.f, sy = 0.f, sz = 0.f;
#pragma unroll
    for (int p = 0; p < PATCHW; p++) {
        sx += sp[p * 3 + 0]; sy += sp[p * 3 + 1]; sz += sp[p * 3 + 2];
    }
    float cx = sx / 32.0f, cy = sy / 32.0f, cz = sz / 32.0f;
    g_cent[m * 3 + 0] = cx; g_cent[m * 3 + 1] = cy; g_cent[m * 3 + 2] = cz;
    if (write_cent) {
        out[TOK + m * 3 + 0] = cx; out[TOK + m * 3 + 1] = cy; out[TOK + m * 3 + 2] = cz;
    }
}

// ---------------- K_hp: hp = relu(cent @ Wp1 + bp1) -> comb[:,128:192] (bf16 split) ----------------
__global__ void __launch_bounds__(128) k_hp(const float* __restrict__ Wp1,
                                            const float* __restrict__ bp1) {
    int t = threadIdx.x;
    int m = blockIdx.x * 2 + (t >> 6);
    int ch = t & 63;
    if (m >= BL) return;
    float cx = g_cent[m * 3 + 0], cy = g_cent[m * 3 + 1], cz = g_cent[m * 3 + 2];
    float v = fmaf(cz, Wp1[128 + ch], fmaf(cy, Wp1[64 + ch], fmaf(cx, Wp1[ch], bp1[ch])));
    v = fmaxf(v, 0.f);
    __nv_bfloat16 hi, mid;
    bf16split(v, hi, mid);
    size_t o = (size_t)m * COMBK + 128 + ch;
    g_comb_hi[o] = hi; g_comb_mid[o] = mid;
}

// ---------------- K_geo: mma.sync bf16-split GEMM + maxpool ----------------
#define GW    16        // windows per block
#define HSTR  72        // bf16 per h row (144B = 9x16B)
#define WSTR  136       // bf16 per W2 row (272B = 17x16B)

__global__ void __launch_bounds__(128) k_geo(const float* __restrict__ W1,
                                             const float* __restrict__ b1,
                                             const float* __restrict__ W2,
                                             const float* __restrict__ b2) {
    __shared__ __align__(16) __nv_bfloat16 w2hi_s[64 * WSTR];
    __shared__ __align__(16) __nv_bfloat16 w2mid_s[64 * WSTR];
    __shared__ __align__(16) __nv_bfloat16 hhi_s[32 * HSTR];
    __shared__ __align__(16) __nv_bfloat16 hmid_s[32 * HSTR];
    __shared__ float W1s[192], b1s[64], b2s[128];

    int t = threadIdx.x, wi = t >> 5, lane = t & 31;

    if (t < 64) {
        W1s[t] = W1[t]; W1s[64 + t] = W1[64 + t]; W1s[128 + t] = W1[128 + t];
        b1s[t] = b1[t];
    }
    b2s[t] = b2[t];
    for (int i = t; i < 8192; i += 128) {
        int k = i >> 7, c = i & 127;
        float v = W2[i];
        __nv_bfloat16 hi, mid;
        bf16split(v, hi, mid);
        w2hi_s[k * WSTR + c]  = hi;
        w2mid_s[k * WSTR + c] = mid;
    }
    __syncthreads();

    uint32_t hhi_b = smem_u32(hhi_s), hmid_b = smem_u32(hmid_s);
    uint32_t w2hi_b = smem_u32(w2hi_s), w2mid_b = smem_u32(w2mid_s);

    int p  = t & 31;
    int kb = (t >> 5) * 16;

    uint32_t aoff = (uint32_t)(lane & 15) * (HSTR * 2) + (uint32_t)((lane >> 4) & 1) * 16;
    uint32_t boff = (uint32_t)(lane & 15) * (WSTR * 2) + (uint32_t)(wi * 32) * 2;

    for (int w = 0; w < GW; w++) {
        int mi = blockIdx.x * GW + w;
        int m  = min(mi, BL - 1);
        int b  = m / LWIN, l = m - b * LWIN;

        {
            const float* sp = g_sp + ((size_t)b * NPTS + (size_t)l * STRIDEW + p) * 3;
            float lx = sp[0] - g_cent[m * 3 + 0];
            float ly = sp[1] - g_cent[m * 3 + 1];
            float lz = sp[2] - g_cent[m * 3 + 2];
#pragma unroll
            for (int j = 0; j < 16; j += 2) {
                int k = kb + j;
                float v0 = fmaxf(fmaf(lz, W1s[128 + k],
                           fmaf(ly, W1s[64 + k], fmaf(lx, W1s[k], b1s[k]))), 0.f);
                float v1 = fmaxf(fmaf(lz, W1s[128 + k + 1],
                           fmaf(ly, W1s[64 + k + 1], fmaf(lx, W1s[k + 1], b1s[k + 1]))), 0.f);
                uint32_t h2;
                asm("cvt.rn.bf16x2.f32 %0, %1, %2;" : "=r"(h2) : "f"(v1), "f"(v0));
                float h0f = __uint_as_float(h2 << 16);
                float h1f = __uint_as_float(h2 & 0xFFFF0000u);
                uint32_t m2;
                asm("cvt.rn.bf16x2.f32 %0, %1, %2;" : "=r"(m2) : "f"(v1 - h1f), "f"(v0 - h0f));
                *(uint32_t*)&hhi_s[p * HSTR + k]  = h2;
                *(uint32_t*)&hmid_s[p * HSTR + k] = m2;
            }
        }
        __syncthreads();

        float acc[2][4][4] = {};
#pragma unroll
        for (int kt = 0; kt < 4; kt++) {
            uint32_t aH[2][4], aM[2][4];
            uint32_t ak = (uint32_t)(kt * 32);
            ldsm4(aH[0], hhi_b  + aoff + ak);
            ldsm4(aH[1], hhi_b  + aoff + ak + 16 * (HSTR * 2));
            ldsm4(aM[0], hmid_b + aoff + ak);
            ldsm4(aM[1], hmid_b + aoff + ak + 16 * (HSTR * 2));
            uint32_t bk = (uint32_t)(kt * 16) * (WSTR * 2);
#pragma unroll
            for (int nt = 0; nt < 4; nt++) {
                uint32_t bH[2], bM[2];
                uint32_t bn = (uint32_t)(nt * 16);
                ldsm2t(bH, w2hi_b  + boff + bk + bn);
                ldsm2t(bM, w2mid_b + boff + bk + bn);
#pragma unroll
                for (int mt = 0; mt < 2; mt++) {
                    mma_bf16(acc[mt][nt], aH[mt], bH);
                    mma_bf16(acc[mt][nt], aH[mt], bM);
                    mma_bf16(acc[mt][nt], aM[mt], bH);
                }
            }
        }

        if (mi < BL) {
#pragma unroll
            for (int nt = 0; nt < 4; nt++) {
                float m0 = fmaxf(fmaxf(acc[0][nt][0], acc[0][nt][2]),
                                 fmaxf(acc[1][nt][0], acc[1][nt][2]));
                float m1 = fmaxf(fmaxf(acc[0][nt][1], acc[0][nt][3]),
                                 fmaxf(acc[1][nt][1], acc[1][nt][3]));
#pragma unroll
                for (int s = 4; s <= 16; s <<= 1) {
                    m0 = fmaxf(m0, __shfl_xor_sync(0xffffffffu, m0, s));
                    m1 = fmaxf(m1, __shfl_xor_sync(0xffffffffu, m1, s));
                }
                if (lane < 4) {
                    int c = wi * 32 + nt * 8 + 2 * lane;
                    float v0 = fmaxf(m0 + b2s[c], 0.f);
                    float v1 = fmaxf(m1 + b2s[c + 1], 0.f);
                    __nv_bfloat16 h0, d0, h1, d1;
                    bf16split(v0, h0, d0);
                    bf16split(v1, h1, d1);
                    size_t o = (size_t)mi * COMBK + c;
                    g_comb_hi[o] = h0;  g_comb_hi[o + 1] = h1;
                    g_comb_mid[o] = d0; g_comb_mid[o + 1] = d1;
                }
            }
        }
        __syncthreads();
    }
}

// ---------------- K7: tokens = comb(BLx192) @ wb(192x256) + bfold  (mma.sync bf16-split) ----------------
#define ASTR 200                         // bf16 per A row (400B = 25x16B)
#define BSTR 72                          // bf16 per B row (144B = 9x16B)
#define PA_HI  0
#define PA_MID (PA_HI + 64 * ASTR * 2)   // 25600
#define PB_HI  (PA_MID + 64 * ASTR * 2)  // 51200
#define PB_MID (PB_HI + 192 * BSTR * 2)  // 78848
#define P_TOTAL (PB_MID + 192 * BSTR * 2) // 106496

__global__ void __launch_bounds__(256) k_proj(float* __restrict__ out) {
    extern __shared__ __align__(16) unsigned char ps[];
    int t = threadIdx.x, wid = t >> 5, lane = t & 31;
    int row0 = blockIdx.x * 64, col0 = blockIdx.y * 64;

    // load A (64 rows x 192 k), hi & mid
#pragma unroll
    for (int j = 0; j < 6; j++) {
        int idx = t + 256 * j;
        int r = idx / 24, kq = (idx % 24) * 8;
        size_t src = (size_t)(row0 + r) * COMBK + kq;
        *(uint4*)(ps + PA_HI  + (r * ASTR + kq) * 2) = *(const uint4*)(g_comb_hi + src);
        *(uint4*)(ps + PA_MID + (r * ASTR + kq) * 2) = *(const uint4*)(g_comb_mid + src);
    }
    // load B (192 k x 64 n), hi & mid
#pragma unroll
    for (int j = 0; j < 6; j++) {
        int idx = t + 256 * j;
        int k = idx / 8, nq = (idx % 8) * 8;
        size_t src = (size_t)k * 256 + col0 + nq;
        *(uint4*)(ps + PB_HI  + (k * BSTR + nq) * 2) = *(const uint4*)(g_wb_hi + src);
        *(uint4*)(ps + PB_MID + (k * BSTR + nq) * 2) = *(const uint4*)(g_wb_mid + src);
    }
    __syncthreads();

    int wm = wid & 1, wn = wid >> 1;     // 2 m-groups x 4 n-groups
    uint32_t aHb = smem_u32(ps + PA_HI), aMb = smem_u32(ps + PA_MID);
    uint32_t bHb = smem_u32(ps + PB_HI), bMb = smem_u32(ps + PB_MID);
    uint32_t aoff = (uint32_t)(lane & 15) * (ASTR * 2) + (uint32_t)((lane >> 4) & 1) * 16;
    uint32_t boff = (uint32_t)(lane & 15) * (BSTR * 2) + (uint32_t)(wn * 16) * 2;

    float acc[2][2][4] = {};
#pragma unroll
    for (int kt = 0; kt < 12; kt++) {
        uint32_t aH[2][4], aM[2][4];
#pragma unroll
        for (int mt = 0; mt < 2; mt++) {
            uint32_t ro = (uint32_t)((wm * 32 + mt * 16) * (ASTR * 2)) + kt * 32;
            ldsm4(aH[mt], aHb + aoff + ro);
            ldsm4(aM[mt], aMb + aoff + ro);
        }
        uint32_t bk = (uint32_t)(kt * 16) * (BSTR * 2);
#pragma unroll
        for (int nt = 0; nt < 2; nt++) {
            uint32_t bH[2], bM[2];
            ldsm2t(bH, bHb + boff + bk + nt * 16);
            ldsm2t(bM, bMb + boff + bk + nt * 16);
#pragma unroll
            for (int mt = 0; mt < 2; mt++) {
                mma_bf16(acc[mt][nt], aH[mt], bH);
                mma_bf16(acc[mt][nt], aH[mt], bM);
                mma_bf16(acc[mt][nt], aM[mt], bH);
            }
        }
    }

#pragma unroll
    for (int mt = 0; mt < 2; mt++)
#pragma unroll
        for (int nt = 0; nt < 2; nt++) {
            int r = row0 + wm * 32 + mt * 16 + (lane >> 2);
            int c = col0 + wn * 16 + nt * 8 + (lane & 3) * 2;
            float b0 = g_bfold[c], b1 = g_bfold[c + 1];
            if (r < BL) {
                out[(size_t)r * 256 + c]     = acc[mt][nt][0] + b0;
                out[(size_t)r * 256 + c + 1] = acc[mt][nt][1] + b1;
            }
            if (r + 8 < BL) {
                out[(size_t)(r + 8) * 256 + c]     = acc[mt][nt][2] + b0;
                out[(size_t)(r + 8) * 256 + c + 1] = acc[mt][nt][3] + b1;
            }
        }
}

// ---------------- launch ----------------
extern "C" void kernel_launch(void* const* d_in, const int* in_sizes, int n_in,
                              void* d_out, int out_size) {
    const float* points = (const float*)d_in[0];
    const float* W1   = (const float*)d_in[1];
    const float* b1   = (const float*)d_in[2];
    const float* W2   = (const float*)d_in[3];
    const float* b2   = (const float*)d_in[4];
    const float* Wp1  = (const float*)d_in[5];
    const float* bp1  = (const float*)d_in[6];
    const float* Wp2  = (const float*)d_in[7];
    const float* bp2  = (const float*)d_in[8];
    const float* Wproj = (const float*)d_in[9];
    const float* bproj = (const float*)d_in[10];
    float* out = (float*)d_out;

    int write_cent = (out_size >= TOK + CEN) ? 1 : 0;
    int write_idx  = (out_size >= TOK + CEN + IDXN) ? 1 : 0;

    cudaFuncSetAttribute(k_proj, cudaFuncAttributeMaxDynamicSharedMemorySize, P_TOTAL);

    k_fold<<<193, 256>>>(Wproj, Wp2, bp2, bproj);
    k_reset<<<1, 64>>>();
    k_minmax<<<BATCH * 64, 256>>>(points);
    k_keys<<<BN / 256, 256>>>(points);

    void* d_temp = nullptr;
    unsigned long long* kin = nullptr;
    unsigned long long* kout = nullptr;
    cudaGetSymbolAddress(&d_temp, g_temp);
    cudaGetSymbolAddress((void**)&kin, g_keys);
    cudaGetSymbolAddress((void**)&kout, g_keys_out);

    // bits [0,17) are n and the input is already n-ascending; stable LSD radix
    // over bits [17,50) preserves that tiebreak order => exact stable argsort
    // with 5 passes instead of 7.
    size_t temp_bytes = 0;
    cub::DeviceRadixSort::SortKeys(nullptr, temp_bytes, kin, kout, BN, 17, 50);
    if (temp_bytes <= sizeof(g_temp)) {
        cub::DeviceRadixSort::SortKeys(d_temp, temp_bytes, kin, kout, BN, 17, 50);
    }

    k_gather<<<BN / 256, 256>>>(points, out, write_idx);
    k_cent<<<(BL + 127) / 128, 128>>>(out, write_cent);
    k_hp<<<(BL + 1) / 2, 128>>>(Wp1, bp1);
    k_geo<<<(BL + GW - 1) / GW, 128>>>(W1, b1, W2, b2);
    k_proj<<<dim3(BLP / 64, 4), 256, P_TOTAL>>>(out);
}